// round 14
// baseline (speedup 1.0000x reference)
#include <cuda_runtime.h>
#include <cuda_fp16.h>
#include <cstddef>
#include <cstdint>

// Problem constants
static constexpr int BATCH  = 4;
static constexpr int SEQ    = 2048;
static constexpr int DMODEL = 1024;
static constexpr int NHEAD  = 16;
static constexpr int DHEAD  = 64;
static constexpr int MROWS  = BATCH * SEQ;   // 8192

// Scratch (device globals). All activations fp16.
__device__ __half g_q[MROWS * DMODEL];       // Q pre-scaled by 0.125*log2(e)
__device__ __half g_k[MROWS * DMODEL];
__device__ __half g_v[MROWS * DMODEL];
__device__ __half g_att[MROWS * DMODEL];
__device__ __half g_xh[MROWS * DMODEL];      // fp16 x
__device__ __half g_wh[4 * DMODEL * DMODEL]; // fp16 W^T (Q,K,V,O), [N][K]

static constexpr float QSCALE = 0.125f * 1.4426950408889634f;  // 1/sqrt(64) * log2(e)

// ---------------- helpers ----------------
__device__ __forceinline__ uint32_t smem_u32(const void* p) {
    return (uint32_t)__cvta_generic_to_shared(p);
}
__device__ __forceinline__ void cp16s(uint32_t smem_dst, const void* gsrc) {
    asm volatile("cp.async.cg.shared.global [%0], [%1], 16;\n" :: "r"(smem_dst), "l"(gsrc));
}
__device__ __forceinline__ void cp16(void* smem_dst, const void* gsrc) {
    cp16s(smem_u32(smem_dst), gsrc);
}
__device__ __forceinline__ void cp_commit() { asm volatile("cp.async.commit_group;\n"); }
template <int N>
__device__ __forceinline__ void cp_wait() { asm volatile("cp.async.wait_group %0;\n" :: "n"(N)); }

// mma.m16n8k16 fp16 in, fp32 accumulate. row.col.
__device__ __forceinline__ void mma16(float& c0, float& c1, float& c2, float& c3,
                                      uint32_t a0, uint32_t a1, uint32_t a2, uint32_t a3,
                                      uint32_t b0, uint32_t b1)
{
    asm volatile(
        "mma.sync.aligned.m16n8k16.row.col.f32.f16.f16.f32 "
        "{%0,%1,%2,%3}, {%4,%5,%6,%7}, {%8,%9}, {%0,%1,%2,%3};\n"
        : "+f"(c0), "+f"(c1), "+f"(c2), "+f"(c3)
        : "r"(a0), "r"(a1), "r"(a2), "r"(a3), "r"(b0), "r"(b1));
}

__device__ __forceinline__ void ldsm4(uint32_t& r0, uint32_t& r1, uint32_t& r2, uint32_t& r3,
                                      uint32_t saddr)
{
    asm volatile("ldmatrix.sync.aligned.m8n8.x4.shared.b16 {%0,%1,%2,%3}, [%4];"
                 : "=r"(r0), "=r"(r1), "=r"(r2), "=r"(r3) : "r"(saddr));
}
__device__ __forceinline__ void ldsm4t(uint32_t& r0, uint32_t& r1, uint32_t& r2, uint32_t& r3,
                                       uint32_t saddr)
{
    asm volatile("ldmatrix.sync.aligned.m8n8.x4.trans.shared.b16 {%0,%1,%2,%3}, [%4];"
                 : "=r"(r0), "=r"(r1), "=r"(r2), "=r"(r3) : "r"(saddr));
}

__device__ __forceinline__ uint32_t packh2(float a, float b) {
    __half2 h = __floats2half2_rn(a, b);
    return *(uint32_t*)&h;
}

// single-instruction exp2
__device__ __forceinline__ float ex2(float x) {
    float r;
    asm("ex2.approx.ftz.f32 %0, %1;" : "=f"(r) : "f"(x));
    return r;
}

// ---------------------------------------------------------------------------
// fp32 -> fp16 elementwise
// ---------------------------------------------------------------------------
__global__ __launch_bounds__(256) void f32_to_f16(const float* __restrict__ in,
                                                  __half* __restrict__ out, int n4)
{
    int i = blockIdx.x * 256 + threadIdx.x;
    if (i < n4) {
        float4 v = ((const float4*)in)[i];
        uint2 u;
        u.x = packh2(v.x, v.y);
        u.y = packh2(v.z, v.w);
        ((uint2*)out)[i] = u;
    }
}

// ---------------------------------------------------------------------------
// Fused: transpose + fp16-round all four 1024x1024 weights (grid.z selects).
// ---------------------------------------------------------------------------
__global__ __launch_bounds__(256) void transpose_w4(
    const float* __restrict__ w0, const float* __restrict__ w1,
    const float* __restrict__ w2, const float* __restrict__ w3,
    __half* __restrict__ o0, __half* __restrict__ o1,
    __half* __restrict__ o2, __half* __restrict__ o3)
{
    const float* in = w0; __half* out = o0;
    if (blockIdx.z == 1) { in = w1; out = o1; }
    else if (blockIdx.z == 2) { in = w2; out = o2; }
    else if (blockIdx.z == 3) { in = w3; out = o3; }

    __shared__ float t[32][33];
    const int bx = blockIdx.x * 32, by = blockIdx.y * 32;
    const int tx = threadIdx.x & 31, ty = threadIdx.x >> 5;
    #pragma unroll
    for (int j = 0; j < 32; j += 8)
        t[ty + j][tx] = in[(long)(by + ty + j) * DMODEL + bx + tx];
    __syncthreads();
    #pragma unroll
    for (int j = 0; j < 32; j += 8)
        out[(long)(bx + ty + j) * DMODEL + by + tx] = __float2half_rn(t[tx][ty + j]);
}

// ---------------------------------------------------------------------------
// fp16 GEMM, 64x64 warp tiles, 3 CTAs/SM. C = A[M,K] * Bt[N,K]^T, fp32 accum.
// Per-z epilogue scale folds the softmax log2-domain Q scaling in.
// ---------------------------------------------------------------------------
static constexpr int HS = 40;                       // halves per smem row
static constexpr int HBUF = 128 * HS;               // halves per buffer
static constexpr int GEMM_SMEM = 4 * HBUF * 2;      // 40960 B

template <int NMAT, bool OUT_HALF>
__global__ __launch_bounds__(128, 3) void gemm_h(
    const __half* __restrict__ A,
    const __half* __restrict__ B0, const __half* __restrict__ B1, const __half* __restrict__ B2,
    void* __restrict__ C0, void* __restrict__ C1, void* __restrict__ C2,
    float esc0, float esc1, float esc2)
{
    extern __shared__ __half hsm[];
    __half* As = hsm;                 // [2][128][40]
    __half* Bs = hsm + 2 * HBUF;      // [2][128][40]

    const __half* Bt = B0;
    void* C = C0;
    float esc = esc0;
    if (NMAT > 1) {
        if (blockIdx.z == 1) { Bt = B1; C = C1; esc = esc1; }
        else if (blockIdx.z == 2) { Bt = B2; C = C2; esc = esc2; }
    }

    const int tid = threadIdx.x;
    const int wid = tid >> 5;
    const int l   = tid & 31;
    const int g   = l >> 2;
    const int qd  = l & 3;
    const int wm  = (wid & 1) * 64;
    const int wn  = (wid >> 1) * 64;
    const long bm0 = (long)blockIdx.y * 128;
    const long bn0 = (long)blockIdx.x * 128;

    const int a_m = (l & 7) + ((l >> 3) & 1) * 8;
    const int a_k = (l >> 4) * 8;
    const int b_n = (l & 7) + (l >> 4) * 8;
    const int b_k = ((l >> 3) & 1) * 8;

    float acc[4][8][4];
    #pragma unroll
    for (int i = 0; i < 4; i++)
        #pragma unroll
        for (int j = 0; j < 8; j++)
            #pragma unroll
            for (int e = 0; e < 4; e++) acc[i][j][e] = 0.0f;

    const uint32_t asb = smem_u32(As);
    const uint32_t bsb = smem_u32(Bs);

    auto load_chunk = [&](int k0, int buf) {
        const uint32_t ab = asb + buf * HBUF * 2;
        const uint32_t bb = bsb + buf * HBUF * 2;
        #pragma unroll
        for (int i = 0; i < 4; i++) {
            int idx = tid + i * 128;
            int row = idx >> 2, ci = idx & 3;
            cp16s(ab + row * (HS * 2) + ci * 16, A  + (bm0 + row) * DMODEL + k0 + ci * 8);
            cp16s(bb + row * (HS * 2) + ci * 16, Bt + (bn0 + row) * DMODEL + k0 + ci * 8);
        }
        cp_commit();
    };

    load_chunk(0, 0);
    cp_wait<0>();
    __syncthreads();

    int cur = 0;
    for (int k0 = 32; k0 <= DMODEL; k0 += 32) {
        const bool more = (k0 < DMODEL);
        if (more) load_chunk(k0, cur ^ 1);

        const uint32_t acb = asb + cur * HBUF * 2;
        const uint32_t bcb = bsb + cur * HBUF * 2;
        #pragma unroll
        for (int ks = 0; ks < 2; ks++) {
            const int kb0 = ks * 16;
            uint32_t af[4][4];
            #pragma unroll
            for (int tm = 0; tm < 4; tm++)
                ldsm4(af[tm][0], af[tm][1], af[tm][2], af[tm][3],
                      acb + ((wm + tm * 16 + a_m) * HS + kb0 + a_k) * 2);
            uint32_t bf[8][2];
            #pragma unroll
            for (int tp = 0; tp < 4; tp++)
                ldsm4(bf[2 * tp][0], bf[2 * tp][1], bf[2 * tp + 1][0], bf[2 * tp + 1][1],
                      bcb + ((wn + tp * 16 + b_n) * HS + kb0 + b_k) * 2);
            #pragma unroll
            for (int tm = 0; tm < 4; tm++)
                #pragma unroll
                for (int tn = 0; tn < 8; tn++)
                    mma16(acc[tm][tn][0], acc[tm][tn][1], acc[tm][tn][2], acc[tm][tn][3],
                          af[tm][0], af[tm][1], af[tm][2], af[tm][3],
                          bf[tn][0], bf[tn][1]);
        }

        if (more) {
            cp_wait<0>();
            __syncthreads();
            cur ^= 1;
        }
    }

    #pragma unroll
    for (int tm = 0; tm < 4; tm++) {
        const long row0 = bm0 + wm + tm * 16 + g;
        const long row1 = row0 + 8;
        #pragma unroll
        for (int tn = 0; tn < 8; tn++) {
            const long col = bn0 + wn + tn * 8 + 2 * qd;
            if (OUT_HALF) {
                __half* Ch = (__half*)C;
                *(uint32_t*)(Ch + row0 * DMODEL + col) =
                    packh2(acc[tm][tn][0] * esc, acc[tm][tn][1] * esc);
                *(uint32_t*)(Ch + row1 * DMODEL + col) =
                    packh2(acc[tm][tn][2] * esc, acc[tm][tn][3] * esc);
            } else {
                float* Cf = (float*)C;
                *(float2*)(Cf + row0 * DMODEL + col) = make_float2(acc[tm][tn][0], acc[tm][tn][1]);
                *(float2*)(Cf + row1 * DMODEL + col) = make_float2(acc[tm][tn][2], acc[tm][tn][3]);
            }
        }
    }
}

// ---------------------------------------------------------------------------
// Flash attention fp16 v11 (causal): 64 q/CTA, 128 thr = 4 warps.
// Heavy-first q-tile ordering (reversed blockIdx.x) to fix the causal tail.
// Base-2 softmax, 3-stage cp.async pipeline, ldmatrix(.trans) frags.
// ---------------------------------------------------------------------------
static constexpr int FS = 72;                         // halves per smem row
static constexpr int FBUF = 64 * FS;                  // halves per stage
static constexpr int NSTAGE = 3;
static constexpr int FL_SMEM = 2 * NSTAGE * FBUF * 2; // 55296 B

__global__ __launch_bounds__(128, 3) void flash11(
    const __half* __restrict__ Qg, const __half* __restrict__ Kg,
    const __half* __restrict__ Vg, __half* __restrict__ Og)
{
    extern __shared__ __half fsm[];
    __half* Ksb = fsm;                    // [3][64][72]
    __half* Vsb = fsm + NSTAGE * FBUF;    // [3][64][72]

    const int tid = threadIdx.x;
    const int w   = tid >> 5;
    const int l   = tid & 31;
    const int g   = l >> 2;
    const int qd  = l & 3;
    const int b = blockIdx.z, h = blockIdx.y;
    const int qt = gridDim.x - 1 - blockIdx.x;   // heavy-first: big qt launches early
    const int q0 = qt * 64;

    const uint32_t ksb_s = smem_u32(Ksb);
    const uint32_t vsb_s = smem_u32(Vsb);

    const int a_m = (l & 7) + ((l >> 3) & 1) * 8;
    const int a_k = (l >> 4) * 8;
    const int b_n = (l & 7) + (l >> 4) * 8;
    const int b_k = ((l >> 3) & 1) * 8;
    const int v_r = l & 15;
    const int v_c = (l >> 4) * 8;

    const long bh_base = (long)b * SEQ * DMODEL + h * DHEAD;

    // ---- Stage Q (already scaled) into Ksb stage 0 via cp.async; pull frags
    {
        const long qoff = bh_base + (long)q0 * DMODEL;
        #pragma unroll
        for (int r = 0; r < 4; r++) {
            int idx = tid + r * 128;
            int row = idx >> 3, c8 = (idx & 7) * 8;
            cp16(&Ksb[row * FS + c8], Qg + qoff + (long)row * DMODEL + c8);
        }
        cp_commit();
        cp_wait<0>();
    }
    __syncthreads();

    uint32_t qa[4][4];
    #pragma unroll
    for (int ks = 0; ks < 4; ks++)
        ldsm4(qa[ks][0], qa[ks][1], qa[ks][2], qa[ks][3],
              ksb_s + ((w * 16 + a_m) * FS + ks * 16 + a_k) * 2);
    __syncthreads();   // Q-frag reads done before tile 0 overwrites stage 0

    float oacc[8][4];
    #pragma unroll
    for (int n = 0; n < 8; n++)
        #pragma unroll
        for (int e = 0; e < 4; e++) oacc[n][e] = 0.0f;
    float m0 = -1e30f, m1 = -1e30f, l0 = 0.0f, l1 = 0.0f;

    const int ntiles = qt + 1;

    auto load_tile = [&](int t, int buf) {
        __half* Kb = Ksb + buf * FBUF;
        __half* Vb = Vsb + buf * FBUF;
        const long off = bh_base + (long)t * 64 * DMODEL;
        #pragma unroll
        for (int r = 0; r < 4; r++) {
            int idx = tid + r * 128;
            int row = idx >> 3, c8 = (idx & 7) * 8;
            cp16(&Kb[row * FS + c8], Kg + off + (long)row * DMODEL + c8);
            cp16(&Vb[row * FS + c8], Vg + off + (long)row * DMODEL + c8);
        }
        cp_commit();
    };

    // prologue: stages 0,1
    load_tile(0, 0);
    if (ntiles > 1) load_tile(1, 1);

    for (int t = 0; t < ntiles; t++) {
        const int cur = t % NSTAGE;
        if (t + 1 < ntiles) cp_wait<1>(); else cp_wait<0>();
        __syncthreads();   // stage t visible; all warps done with stage (t-1)

        if (t + 2 < ntiles) load_tile(t + 2, (t + 2) % NSTAGE);

        const uint32_t ks_s = ksb_s + cur * FBUF * 2;
        const uint32_t vs_s = vsb_s + cur * FBUF * 2;

        // ---- S = Q * K^T (log2-domain scores)
        float sacc[8][4];
        #pragma unroll
        for (int n = 0; n < 8; n++)
            sacc[n][0] = sacc[n][1] = sacc[n][2] = sacc[n][3] = 0.0f;
        #pragma unroll
        for (int ks = 0; ks < 4; ks++) {
            uint32_t kf[8][2];
            #pragma unroll
            for (int p = 0; p < 4; p++)
                ldsm4(kf[2 * p][0], kf[2 * p][1], kf[2 * p + 1][0], kf[2 * p + 1][1],
                      ks_s + ((p * 16 + b_n) * FS + ks * 16 + b_k) * 2);
            #pragma unroll
            for (int n = 0; n < 8; n++)
                mma16(sacc[n][0], sacc[n][1], sacc[n][2], sacc[n][3],
                      qa[ks][0], qa[ks][1], qa[ks][2], qa[ks][3],
                      kf[n][0], kf[n][1]);
        }

        // ---- causal mask (diagonal tile only)
        if (t == ntiles - 1) {
            const int r0 = w * 16 + g, r1 = r0 + 8;
            #pragma unroll
            for (int n = 0; n < 8; n++) {
                int c0 = n * 8 + 2 * qd, c1 = c0 + 1;
                if (c0 > r0) sacc[n][0] = -1e30f;
                if (c1 > r0) sacc[n][1] = -1e30f;
                if (c0 > r1) sacc[n][2] = -1e30f;
                if (c1 > r1) sacc[n][3] = -1e30f;
            }
        }

        // ---- online softmax (base 2, registers)
        float mx0 = -1e30f, mx1 = -1e30f;
        #pragma unroll
        for (int n = 0; n < 8; n++) {
            mx0 = fmaxf(mx0, fmaxf(sacc[n][0], sacc[n][1]));
            mx1 = fmaxf(mx1, fmaxf(sacc[n][2], sacc[n][3]));
        }
        mx0 = fmaxf(mx0, __shfl_xor_sync(0xffffffffu, mx0, 1));
        mx0 = fmaxf(mx0, __shfl_xor_sync(0xffffffffu, mx0, 2));
        mx1 = fmaxf(mx1, __shfl_xor_sync(0xffffffffu, mx1, 1));
        mx1 = fmaxf(mx1, __shfl_xor_sync(0xffffffffu, mx1, 2));
        const float mn0 = fmaxf(m0, mx0);
        const float mn1 = fmaxf(m1, mx1);
        const float cr0 = ex2(m0 - mn0);
        const float cr1 = ex2(m1 - mn1);

        uint32_t pp0[8], pp1[8];
        float s0 = 0.0f, s1 = 0.0f;
        #pragma unroll
        for (int n = 0; n < 8; n++) {
            float p0 = ex2(sacc[n][0] - mn0);
            float p1 = ex2(sacc[n][1] - mn0);
            float p2 = ex2(sacc[n][2] - mn1);
            float p3 = ex2(sacc[n][3] - mn1);
            s0 += p0 + p1;
            s1 += p2 + p3;
            pp0[n] = packh2(p0, p1);
            pp1[n] = packh2(p2, p3);
        }
        s0 += __shfl_xor_sync(0xffffffffu, s0, 1);
        s0 += __shfl_xor_sync(0xffffffffu, s0, 2);
        s1 += __shfl_xor_sync(0xffffffffu, s1, 1);
        s1 += __shfl_xor_sync(0xffffffffu, s1, 2);
        l0 = l0 * cr0 + s0;
        l1 = l1 * cr1 + s1;
        m0 = mn0;
        m1 = mn1;

        #pragma unroll
        for (int n = 0; n < 8; n++) {
            oacc[n][0] *= cr0; oacc[n][1] *= cr0;
            oacc[n][2] *= cr1; oacc[n][3] *= cr1;
        }

        // ---- O += P * V  (P regs; V^T frags via ldmatrix.trans)
        #pragma unroll
        for (int ks = 0; ks < 4; ks++) {
            const uint32_t a0 = pp0[2 * ks],     a1 = pp1[2 * ks];
            const uint32_t a2 = pp0[2 * ks + 1], a3 = pp1[2 * ks + 1];
            #pragma unroll
            for (int p = 0; p < 4; p++) {
                uint32_t v0, v1, v2, v3;
                ldsm4t(v0, v1, v2, v3,
                       vs_s + ((ks * 16 + v_r) * FS + p * 16 + v_c) * 2);
                mma16(oacc[2 * p][0], oacc[2 * p][1], oacc[2 * p][2], oacc[2 * p][3],
                      a0, a1, a2, a3, v0, v1);
                mma16(oacc[2 * p + 1][0], oacc[2 * p + 1][1], oacc[2 * p + 1][2], oacc[2 * p + 1][3],
                      a0, a1, a2, a3, v2, v3);
            }
        }
    }

    // ---- epilogue: normalize, write fp16
    const float inv0 = 1.0f / l0;
    const float inv1 = 1.0f / l1;
    const long row0 = (long)(b * SEQ + q0 + w * 16 + g);
    const long row1 = row0 + 8;
    #pragma unroll
    for (int n = 0; n < 8; n++) {
        int c = h * DHEAD + n * 8 + 2 * qd;
        *(uint32_t*)(Og + row0 * DMODEL + c) = packh2(oacc[n][0] * inv0, oacc[n][1] * inv0);
        *(uint32_t*)(Og + row1 * DMODEL + c) = packh2(oacc[n][2] * inv1, oacc[n][3] * inv1);
    }
}

// ---------------------------------------------------------------------------
// Launch
// ---------------------------------------------------------------------------
extern "C" void kernel_launch(void* const* d_in, const int* in_sizes, int n_in,
                              void* d_out, int out_size)
{
    const float* x  = (const float*)d_in[0];
    const float* wq = (const float*)d_in[1];
    const float* wk = (const float*)d_in[2];
    const float* wv = (const float*)d_in[3];
    const float* wo = (const float*)d_in[4];
    float* out = (float*)d_out;

    __half *qb, *kb, *vb, *ab, *xh, *wh;
    cudaGetSymbolAddress((void**)&qb, g_q);
    cudaGetSymbolAddress((void**)&kb, g_k);
    cudaGetSymbolAddress((void**)&vb, g_v);
    cudaGetSymbolAddress((void**)&ab, g_att);
    cudaGetSymbolAddress((void**)&xh, g_xh);
    cudaGetSymbolAddress((void**)&wh, g_wh);

    __half* wqt = wh;
    __half* wkt = wh + (size_t)DMODEL * DMODEL;
    __half* wvt = wh + 2 * (size_t)DMODEL * DMODEL;
    __half* wot = wh + 3 * (size_t)DMODEL * DMODEL;

    // Pre-passes
    const int NX4 = MROWS * DMODEL / 4;
    f32_to_f16<<<(NX4 + 255) / 256, 256>>>(x, xh, NX4);
    dim3 tg(DMODEL / 32, DMODEL / 32, 4);
    transpose_w4<<<tg, 256>>>(wq, wk, wv, wo, wqt, wkt, wvt, wot);

    cudaFuncSetAttribute((const void*)gemm_h<3, true>,  cudaFuncAttributeMaxDynamicSharedMemorySize, GEMM_SMEM);
    cudaFuncSetAttribute((const void*)gemm_h<1, false>, cudaFuncAttributeMaxDynamicSharedMemorySize, GEMM_SMEM);

    // Fused QKV projection (fp16 out; Q scaled to log2 domain in epilogue)
    dim3 gq(DMODEL / 128, MROWS / 128, 3);   // (8, 64, 3)
    gemm_h<3, true><<<gq, 128, GEMM_SMEM>>>(xh, wqt, wkt, wvt, qb, kb, vb,
                                            QSCALE, 1.0f, 1.0f);

    cudaFuncSetAttribute(flash11, cudaFuncAttributeMaxDynamicSharedMemorySize, FL_SMEM);
    dim3 fg(SEQ / 64, NHEAD, BATCH);         // (32, 16, 4)
    flash11<<<fg, 128, FL_SMEM>>>(qb, kb, vb, ab);

    // Output projection (fp32 out)
    dim3 go(DMODEL / 128, MROWS / 128, 1);   // (8, 64)
    gemm_h<1, false><<<go, 128, GEMM_SMEM>>>(ab, wot, nullptr, nullptr, out, nullptr, nullptr,
                                             1.0f, 1.0f, 1.0f);
}

// round 16
// speedup vs baseline: 1.0843x; 1.0843x over previous
#include <cuda_runtime.h>
#include <cuda_fp16.h>
#include <cstddef>
#include <cstdint>

// Problem constants
static constexpr int BATCH  = 4;
static constexpr int SEQ    = 2048;
static constexpr int DMODEL = 1024;
static constexpr int NHEAD  = 16;
static constexpr int DHEAD  = 64;
static constexpr int MROWS  = BATCH * SEQ;   // 8192

// Scratch (device globals). All activations fp16.
__device__ __half g_q[MROWS * DMODEL];       // Q pre-scaled by 0.125*log2(e)
__device__ __half g_k[MROWS * DMODEL];
__device__ __half g_v[MROWS * DMODEL];
__device__ __half g_att[MROWS * DMODEL];
__device__ __half g_xh[MROWS * DMODEL];      // fp16 x
__device__ __half g_wh[4 * DMODEL * DMODEL]; // fp16 W^T (Q,K,V,O), [N][K]

static constexpr float QSCALE = 0.125f * 1.4426950408889634f;  // 1/sqrt(64) * log2(e)

// ---------------- helpers ----------------
__device__ __forceinline__ uint32_t smem_u32(const void* p) {
    return (uint32_t)__cvta_generic_to_shared(p);
}
__device__ __forceinline__ void cp16s(uint32_t smem_dst, const void* gsrc) {
    asm volatile("cp.async.cg.shared.global [%0], [%1], 16;\n" :: "r"(smem_dst), "l"(gsrc));
}
__device__ __forceinline__ void cp16(void* smem_dst, const void* gsrc) {
    cp16s(smem_u32(smem_dst), gsrc);
}
__device__ __forceinline__ void cp_commit() { asm volatile("cp.async.commit_group;\n"); }
template <int N>
__device__ __forceinline__ void cp_wait() { asm volatile("cp.async.wait_group %0;\n" :: "n"(N)); }

// mma.m16n8k16 fp16 in, fp32 accumulate. row.col.
__device__ __forceinline__ void mma16(float& c0, float& c1, float& c2, float& c3,
                                      uint32_t a0, uint32_t a1, uint32_t a2, uint32_t a3,
                                      uint32_t b0, uint32_t b1)
{
    asm volatile(
        "mma.sync.aligned.m16n8k16.row.col.f32.f16.f16.f32 "
        "{%0,%1,%2,%3}, {%4,%5,%6,%7}, {%8,%9}, {%0,%1,%2,%3};\n"
        : "+f"(c0), "+f"(c1), "+f"(c2), "+f"(c3)
        : "r"(a0), "r"(a1), "r"(a2), "r"(a3), "r"(b0), "r"(b1));
}

__device__ __forceinline__ void ldsm4(uint32_t& r0, uint32_t& r1, uint32_t& r2, uint32_t& r3,
                                      uint32_t saddr)
{
    asm volatile("ldmatrix.sync.aligned.m8n8.x4.shared.b16 {%0,%1,%2,%3}, [%4];"
                 : "=r"(r0), "=r"(r1), "=r"(r2), "=r"(r3) : "r"(saddr));
}
__device__ __forceinline__ void ldsm4t(uint32_t& r0, uint32_t& r1, uint32_t& r2, uint32_t& r3,
                                       uint32_t saddr)
{
    asm volatile("ldmatrix.sync.aligned.m8n8.x4.trans.shared.b16 {%0,%1,%2,%3}, [%4];"
                 : "=r"(r0), "=r"(r1), "=r"(r2), "=r"(r3) : "r"(saddr));
}

__device__ __forceinline__ uint32_t packh2(float a, float b) {
    __half2 h = __floats2half2_rn(a, b);
    return *(uint32_t*)&h;
}

// single-instruction exp2
__device__ __forceinline__ float ex2(float x) {
    float r;
    asm("ex2.approx.ftz.f32 %0, %1;" : "=f"(r) : "f"(x));
    return r;
}

// ---------------------------------------------------------------------------
// fp32 -> fp16 elementwise
// ---------------------------------------------------------------------------
__global__ __launch_bounds__(256) void f32_to_f16(const float* __restrict__ in,
                                                  __half* __restrict__ out, int n4)
{
    int i = blockIdx.x * 256 + threadIdx.x;
    if (i < n4) {
        float4 v = ((const float4*)in)[i];
        uint2 u;
        u.x = packh2(v.x, v.y);
        u.y = packh2(v.z, v.w);
        ((uint2*)out)[i] = u;
    }
}

// ---------------------------------------------------------------------------
// Fused: transpose + fp16-round all four 1024x1024 weights (grid.z selects).
// ---------------------------------------------------------------------------
__global__ __launch_bounds__(256) void transpose_w4(
    const float* __restrict__ w0, const float* __restrict__ w1,
    const float* __restrict__ w2, const float* __restrict__ w3,
    __half* __restrict__ o0, __half* __restrict__ o1,
    __half* __restrict__ o2, __half* __restrict__ o3)
{
    const float* in = w0; __half* out = o0;
    if (blockIdx.z == 1) { in = w1; out = o1; }
    else if (blockIdx.z == 2) { in = w2; out = o2; }
    else if (blockIdx.z == 3) { in = w3; out = o3; }

    __shared__ float t[32][33];
    const int bx = blockIdx.x * 32, by = blockIdx.y * 32;
    const int tx = threadIdx.x & 31, ty = threadIdx.x >> 5;
    #pragma unroll
    for (int j = 0; j < 32; j += 8)
        t[ty + j][tx] = in[(long)(by + ty + j) * DMODEL + bx + tx];
    __syncthreads();
    #pragma unroll
    for (int j = 0; j < 32; j += 8)
        out[(long)(bx + ty + j) * DMODEL + by + tx] = __float2half_rn(t[tx][ty + j]);
}

// ---------------------------------------------------------------------------
// fp16 GEMM, 64x64 warp tiles, 2 CTAs/SM (R13 config — 3 CTAs spilled).
// C = A[M,K] * Bt[N,K]^T, fp32 accum. Per-z epilogue scale.
// ---------------------------------------------------------------------------
static constexpr int HS = 40;                       // halves per smem row
static constexpr int HBUF = 128 * HS;               // halves per buffer
static constexpr int GEMM_SMEM = 4 * HBUF * 2;      // 40960 B

template <int NMAT, bool OUT_HALF>
__global__ __launch_bounds__(128, 2) void gemm_h(
    const __half* __restrict__ A,
    const __half* __restrict__ B0, const __half* __restrict__ B1, const __half* __restrict__ B2,
    void* __restrict__ C0, void* __restrict__ C1, void* __restrict__ C2,
    float esc0, float esc1, float esc2)
{
    extern __shared__ __half hsm[];
    __half* As = hsm;                 // [2][128][40]
    __half* Bs = hsm + 2 * HBUF;      // [2][128][40]

    const __half* Bt = B0;
    void* C = C0;
    float esc = esc0;
    if (NMAT > 1) {
        if (blockIdx.z == 1) { Bt = B1; C = C1; esc = esc1; }
        else if (blockIdx.z == 2) { Bt = B2; C = C2; esc = esc2; }
    }

    const int tid = threadIdx.x;
    const int wid = tid >> 5;
    const int l   = tid & 31;
    const int g   = l >> 2;
    const int qd  = l & 3;
    const int wm  = (wid & 1) * 64;
    const int wn  = (wid >> 1) * 64;
    const long bm0 = (long)blockIdx.y * 128;
    const long bn0 = (long)blockIdx.x * 128;

    const int a_m = (l & 7) + ((l >> 3) & 1) * 8;
    const int a_k = (l >> 4) * 8;
    const int b_n = (l & 7) + (l >> 4) * 8;
    const int b_k = ((l >> 3) & 1) * 8;

    float acc[4][8][4];
    #pragma unroll
    for (int i = 0; i < 4; i++)
        #pragma unroll
        for (int j = 0; j < 8; j++)
            #pragma unroll
            for (int e = 0; e < 4; e++) acc[i][j][e] = 0.0f;

    const uint32_t asb = smem_u32(As);
    const uint32_t bsb = smem_u32(Bs);

    auto load_chunk = [&](int k0, int buf) {
        const uint32_t ab = asb + buf * HBUF * 2;
        const uint32_t bb = bsb + buf * HBUF * 2;
        #pragma unroll
        for (int i = 0; i < 4; i++) {
            int idx = tid + i * 128;
            int row = idx >> 2, ci = idx & 3;
            cp16s(ab + row * (HS * 2) + ci * 16, A  + (bm0 + row) * DMODEL + k0 + ci * 8);
            cp16s(bb + row * (HS * 2) + ci * 16, Bt + (bn0 + row) * DMODEL + k0 + ci * 8);
        }
        cp_commit();
    };

    load_chunk(0, 0);
    cp_wait<0>();
    __syncthreads();

    int cur = 0;
    for (int k0 = 32; k0 <= DMODEL; k0 += 32) {
        const bool more = (k0 < DMODEL);
        if (more) load_chunk(k0, cur ^ 1);

        const uint32_t acb = asb + cur * HBUF * 2;
        const uint32_t bcb = bsb + cur * HBUF * 2;
        #pragma unroll
        for (int ks = 0; ks < 2; ks++) {
            const int kb0 = ks * 16;
            uint32_t af[4][4];
            #pragma unroll
            for (int tm = 0; tm < 4; tm++)
                ldsm4(af[tm][0], af[tm][1], af[tm][2], af[tm][3],
                      acb + ((wm + tm * 16 + a_m) * HS + kb0 + a_k) * 2);
            uint32_t bf[8][2];
            #pragma unroll
            for (int tp = 0; tp < 4; tp++)
                ldsm4(bf[2 * tp][0], bf[2 * tp][1], bf[2 * tp + 1][0], bf[2 * tp + 1][1],
                      bcb + ((wn + tp * 16 + b_n) * HS + kb0 + b_k) * 2);
            #pragma unroll
            for (int tm = 0; tm < 4; tm++)
                #pragma unroll
                for (int tn = 0; tn < 8; tn++)
                    mma16(acc[tm][tn][0], acc[tm][tn][1], acc[tm][tn][2], acc[tm][tn][3],
                          af[tm][0], af[tm][1], af[tm][2], af[tm][3],
                          bf[tn][0], bf[tn][1]);
        }

        if (more) {
            cp_wait<0>();
            __syncthreads();
            cur ^= 1;
        }
    }

    #pragma unroll
    for (int tm = 0; tm < 4; tm++) {
        const long row0 = bm0 + wm + tm * 16 + g;
        const long row1 = row0 + 8;
        #pragma unroll
        for (int tn = 0; tn < 8; tn++) {
            const long col = bn0 + wn + tn * 8 + 2 * qd;
            if (OUT_HALF) {
                __half* Ch = (__half*)C;
                *(uint32_t*)(Ch + row0 * DMODEL + col) =
                    packh2(acc[tm][tn][0] * esc, acc[tm][tn][1] * esc);
                *(uint32_t*)(Ch + row1 * DMODEL + col) =
                    packh2(acc[tm][tn][2] * esc, acc[tm][tn][3] * esc);
            } else {
                float* Cf = (float*)C;
                *(float2*)(Cf + row0 * DMODEL + col) = make_float2(acc[tm][tn][0], acc[tm][tn][1]);
                *(float2*)(Cf + row1 * DMODEL + col) = make_float2(acc[tm][tn][2], acc[tm][tn][3]);
            }
        }
    }
}

// ---------------------------------------------------------------------------
// Flash attention fp16 v12 (causal): 64 q/CTA, 128 thr = 4 warps.
// Heavy-first q-tile ordering. Base-2 softmax with DEFERRED l-reduction:
// per-lane partial row-sums accumulate locally (cr is quad-uniform), quad
// shfl-reduced only in the epilogue -> 4 fewer shfls per tile.
// 3-stage cp.async pipeline, ldmatrix(.trans) frags.
// ---------------------------------------------------------------------------
static constexpr int FS = 72;                         // halves per smem row
static constexpr int FBUF = 64 * FS;                  // halves per stage
static constexpr int NSTAGE = 3;
static constexpr int FL_SMEM = 2 * NSTAGE * FBUF * 2; // 55296 B

__global__ __launch_bounds__(128, 3) void flash12(
    const __half* __restrict__ Qg, const __half* __restrict__ Kg,
    const __half* __restrict__ Vg, __half* __restrict__ Og)
{
    extern __shared__ __half fsm[];
    __half* Ksb = fsm;                    // [3][64][72]
    __half* Vsb = fsm + NSTAGE * FBUF;    // [3][64][72]

    const int tid = threadIdx.x;
    const int w   = tid >> 5;
    const int l   = tid & 31;
    const int g   = l >> 2;
    const int qd  = l & 3;
    const int b = blockIdx.z, h = blockIdx.y;
    const int qt = gridDim.x - 1 - blockIdx.x;   // heavy-first
    const int q0 = qt * 64;

    const uint32_t ksb_s = smem_u32(Ksb);
    const uint32_t vsb_s = smem_u32(Vsb);

    const int a_m = (l & 7) + ((l >> 3) & 1) * 8;
    const int a_k = (l >> 4) * 8;
    const int b_n = (l & 7) + (l >> 4) * 8;
    const int b_k = ((l >> 3) & 1) * 8;
    const int v_r = l & 15;
    const int v_c = (l >> 4) * 8;

    const long bh_base = (long)b * SEQ * DMODEL + h * DHEAD;

    // ---- Stage Q (already scaled) into Ksb stage 0 via cp.async; pull frags
    {
        const long qoff = bh_base + (long)q0 * DMODEL;
        #pragma unroll
        for (int r = 0; r < 4; r++) {
            int idx = tid + r * 128;
            int row = idx >> 3, c8 = (idx & 7) * 8;
            cp16(&Ksb[row * FS + c8], Qg + qoff + (long)row * DMODEL + c8);
        }
        cp_commit();
        cp_wait<0>();
    }
    __syncthreads();

    uint32_t qa[4][4];
    #pragma unroll
    for (int ks = 0; ks < 4; ks++)
        ldsm4(qa[ks][0], qa[ks][1], qa[ks][2], qa[ks][3],
              ksb_s + ((w * 16 + a_m) * FS + ks * 16 + a_k) * 2);
    __syncthreads();   // Q-frag reads done before tile 0 overwrites stage 0

    float oacc[8][4];
    #pragma unroll
    for (int n = 0; n < 8; n++)
        #pragma unroll
        for (int e = 0; e < 4; e++) oacc[n][e] = 0.0f;
    float m0 = -1e30f, m1 = -1e30f;
    float l0 = 0.0f, l1 = 0.0f;          // PER-LANE partial sums

    const int ntiles = qt + 1;

    auto load_tile = [&](int t, int buf) {
        __half* Kb = Ksb + buf * FBUF;
        __half* Vb = Vsb + buf * FBUF;
        const long off = bh_base + (long)t * 64 * DMODEL;
        #pragma unroll
        for (int r = 0; r < 4; r++) {
            int idx = tid + r * 128;
            int row = idx >> 3, c8 = (idx & 7) * 8;
            cp16(&Kb[row * FS + c8], Kg + off + (long)row * DMODEL + c8);
            cp16(&Vb[row * FS + c8], Vg + off + (long)row * DMODEL + c8);
        }
        cp_commit();
    };

    // prologue: stages 0,1
    load_tile(0, 0);
    if (ntiles > 1) load_tile(1, 1);

    for (int t = 0; t < ntiles; t++) {
        const int cur = t % NSTAGE;
        if (t + 1 < ntiles) cp_wait<1>(); else cp_wait<0>();
        __syncthreads();   // stage t visible; all warps done with stage (t-1)

        if (t + 2 < ntiles) load_tile(t + 2, (t + 2) % NSTAGE);

        const uint32_t ks_s = ksb_s + cur * FBUF * 2;
        const uint32_t vs_s = vsb_s + cur * FBUF * 2;

        // ---- S = Q * K^T (log2-domain scores)
        float sacc[8][4];
        #pragma unroll
        for (int n = 0; n < 8; n++)
            sacc[n][0] = sacc[n][1] = sacc[n][2] = sacc[n][3] = 0.0f;
        #pragma unroll
        for (int ks = 0; ks < 4; ks++) {
            uint32_t kf[8][2];
            #pragma unroll
            for (int p = 0; p < 4; p++)
                ldsm4(kf[2 * p][0], kf[2 * p][1], kf[2 * p + 1][0], kf[2 * p + 1][1],
                      ks_s + ((p * 16 + b_n) * FS + ks * 16 + b_k) * 2);
            #pragma unroll
            for (int n = 0; n < 8; n++)
                mma16(sacc[n][0], sacc[n][1], sacc[n][2], sacc[n][3],
                      qa[ks][0], qa[ks][1], qa[ks][2], qa[ks][3],
                      kf[n][0], kf[n][1]);
        }

        // ---- causal mask (diagonal tile only)
        if (t == ntiles - 1) {
            const int r0 = w * 16 + g, r1 = r0 + 8;
            #pragma unroll
            for (int n = 0; n < 8; n++) {
                int c0 = n * 8 + 2 * qd, c1 = c0 + 1;
                if (c0 > r0) sacc[n][0] = -1e30f;
                if (c1 > r0) sacc[n][1] = -1e30f;
                if (c0 > r1) sacc[n][2] = -1e30f;
                if (c1 > r1) sacc[n][3] = -1e30f;
            }
        }

        // ---- online softmax (base 2; max quad-reduced, sum deferred)
        float mx0 = -1e30f, mx1 = -1e30f;
        #pragma unroll
        for (int n = 0; n < 8; n++) {
            mx0 = fmaxf(mx0, fmaxf(sacc[n][0], sacc[n][1]));
            mx1 = fmaxf(mx1, fmaxf(sacc[n][2], sacc[n][3]));
        }
        mx0 = fmaxf(mx0, __shfl_xor_sync(0xffffffffu, mx0, 1));
        mx0 = fmaxf(mx0, __shfl_xor_sync(0xffffffffu, mx0, 2));
        mx1 = fmaxf(mx1, __shfl_xor_sync(0xffffffffu, mx1, 1));
        mx1 = fmaxf(mx1, __shfl_xor_sync(0xffffffffu, mx1, 2));
        const float mn0 = fmaxf(m0, mx0);
        const float mn1 = fmaxf(m1, mx1);
        const float cr0 = ex2(m0 - mn0);
        const float cr1 = ex2(m1 - mn1);

        uint32_t pp0[8], pp1[8];
        float s0 = 0.0f, s1 = 0.0f;
        #pragma unroll
        for (int n = 0; n < 8; n++) {
            float p0 = ex2(sacc[n][0] - mn0);
            float p1 = ex2(sacc[n][1] - mn0);
            float p2 = ex2(sacc[n][2] - mn1);
            float p3 = ex2(sacc[n][3] - mn1);
            s0 += p0 + p1;
            s1 += p2 + p3;
            pp0[n] = packh2(p0, p1);
            pp1[n] = packh2(p2, p3);
        }
        // deferred: keep per-lane partials (cr is quad-uniform, so this is exact)
        l0 = l0 * cr0 + s0;
        l1 = l1 * cr1 + s1;
        m0 = mn0;
        m1 = mn1;

        #pragma unroll
        for (int n = 0; n < 8; n++) {
            oacc[n][0] *= cr0; oacc[n][1] *= cr0;
            oacc[n][2] *= cr1; oacc[n][3] *= cr1;
        }

        // ---- O += P * V  (P regs; V^T frags via ldmatrix.trans)
        #pragma unroll
        for (int ks = 0; ks < 4; ks++) {
            const uint32_t a0 = pp0[2 * ks],     a1 = pp1[2 * ks];
            const uint32_t a2 = pp0[2 * ks + 1], a3 = pp1[2 * ks + 1];
            #pragma unroll
            for (int p = 0; p < 4; p++) {
                uint32_t v0, v1, v2, v3;
                ldsm4t(v0, v1, v2, v3,
                       vs_s + ((ks * 16 + v_r) * FS + p * 16 + v_c) * 2);
                mma16(oacc[2 * p][0], oacc[2 * p][1], oacc[2 * p][2], oacc[2 * p][3],
                      a0, a1, a2, a3, v0, v1);
                mma16(oacc[2 * p + 1][0], oacc[2 * p + 1][1], oacc[2 * p + 1][2], oacc[2 * p + 1][3],
                      a0, a1, a2, a3, v2, v3);
            }
        }
    }

    // ---- epilogue: reduce deferred l across the quad, normalize, write fp16
    l0 += __shfl_xor_sync(0xffffffffu, l0, 1);
    l0 += __shfl_xor_sync(0xffffffffu, l0, 2);
    l1 += __shfl_xor_sync(0xffffffffu, l1, 1);
    l1 += __shfl_xor_sync(0xffffffffu, l1, 2);
    const float inv0 = 1.0f / l0;
    const float inv1 = 1.0f / l1;
    const long row0 = (long)(b * SEQ + q0 + w * 16 + g);
    const long row1 = row0 + 8;
    #pragma unroll
    for (int n = 0; n < 8; n++) {
        int c = h * DHEAD + n * 8 + 2 * qd;
        *(uint32_t*)(Og + row0 * DMODEL + c) = packh2(oacc[n][0] * inv0, oacc[n][1] * inv0);
        *(uint32_t*)(Og + row1 * DMODEL + c) = packh2(oacc[n][2] * inv1, oacc[n][3] * inv1);
    }
}

// ---------------------------------------------------------------------------
// Launch
// ---------------------------------------------------------------------------
extern "C" void kernel_launch(void* const* d_in, const int* in_sizes, int n_in,
                              void* d_out, int out_size)
{
    const float* x  = (const float*)d_in[0];
    const float* wq = (const float*)d_in[1];
    const float* wk = (const float*)d_in[2];
    const float* wv = (const float*)d_in[3];
    const float* wo = (const float*)d_in[4];
    float* out = (float*)d_out;

    __half *qb, *kb, *vb, *ab, *xh, *wh;
    cudaGetSymbolAddress((void**)&qb, g_q);
    cudaGetSymbolAddress((void**)&kb, g_k);
    cudaGetSymbolAddress((void**)&vb, g_v);
    cudaGetSymbolAddress((void**)&ab, g_att);
    cudaGetSymbolAddress((void**)&xh, g_xh);
    cudaGetSymbolAddress((void**)&wh, g_wh);

    __half* wqt = wh;
    __half* wkt = wh + (size_t)DMODEL * DMODEL;
    __half* wvt = wh + 2 * (size_t)DMODEL * DMODEL;
    __half* wot = wh + 3 * (size_t)DMODEL * DMODEL;

    // Pre-passes
    const int NX4 = MROWS * DMODEL / 4;
    f32_to_f16<<<(NX4 + 255) / 256, 256>>>(x, xh, NX4);
    dim3 tg(DMODEL / 32, DMODEL / 32, 4);
    transpose_w4<<<tg, 256>>>(wq, wk, wv, wo, wqt, wkt, wvt, wot);

    cudaFuncSetAttribute((const void*)gemm_h<3, true>,  cudaFuncAttributeMaxDynamicSharedMemorySize, GEMM_SMEM);
    cudaFuncSetAttribute((const void*)gemm_h<1, false>, cudaFuncAttributeMaxDynamicSharedMemorySize, GEMM_SMEM);

    // Fused QKV projection (fp16 out; Q scaled to log2 domain in epilogue)
    dim3 gq(DMODEL / 128, MROWS / 128, 3);   // (8, 64, 3)
    gemm_h<3, true><<<gq, 128, GEMM_SMEM>>>(xh, wqt, wkt, wvt, qb, kb, vb,
                                            QSCALE, 1.0f, 1.0f);

    cudaFuncSetAttribute(flash12, cudaFuncAttributeMaxDynamicSharedMemorySize, FL_SMEM);
    dim3 fg(SEQ / 64, NHEAD, BATCH);         // (32, 16, 4)
    flash12<<<fg, 128, FL_SMEM>>>(qb, kb, vb, ab);

    // Output projection (fp32 out)
    dim3 go(DMODEL / 128, MROWS / 128, 1);   // (8, 64)
    gemm_h<1, false><<<go, 128, GEMM_SMEM>>>(ab, wot, nullptr, nullptr, out, nullptr, nullptr,
                                             1.0f, 1.0f, 1.0f);
}